// round 7
// baseline (speedup 1.0000x reference)
#include <cuda_runtime.h>
#include <cuda_bf16.h>
#include <cstdint>
#include <math.h>

#define B_ 128
#define N_ 784
#define C_ 512
#define K_ 64
#define NSPLIT 14
#define NPER 56   // 784/14

// rows padded to 72 bf16 (144B): ldmatrix row stride 36 words -> 8 rows cover
// banks 0-31 exactly once per 16B fetch group (conflict-free)
#define APAD 72

// ---------------- scratch (no allocations allowed) -------------------------
__device__ __align__(16) __nv_bfloat16 g_an_bf16[8][K_][APAD];   // per-chunk anchor tiles
__device__ float g_lsS[B_ * N_];
__device__ float g_mix[B_ * N_];
__device__ float4 g_part[NSPLIT * B_ * C_ / 4];

__device__ __forceinline__ uint32_t smem_u32(const void* p) {
    uint32_t a;
    asm("{ .reg .u64 t; cvta.to.shared.u64 t, %1; cvt.u32.u64 %0, t; }" : "=r"(a) : "l"(p));
    return a;
}

#define LDSM4(r0, r1, r2, r3, addr) \
    asm volatile("ldmatrix.sync.aligned.m8n8.x4.shared.b16 {%0,%1,%2,%3}, [%4];" \
                 : "=r"(r0), "=r"(r1), "=r"(r2), "=r"(r3) : "r"(addr))

__device__ __forceinline__ void mma_bf16(float d[4], const uint32_t a[4],
                                         uint32_t b0, uint32_t b1) {
    asm volatile(
        "mma.sync.aligned.m16n8k16.row.col.f32.bf16.bf16.f32 "
        "{%0,%1,%2,%3}, {%4,%5,%6,%7}, {%8,%9}, {%0,%1,%2,%3};"
        : "+f"(d[0]), "+f"(d[1]), "+f"(d[2]), "+f"(d[3])
        : "r"(a[0]), "r"(a[1]), "r"(a[2]), "r"(a[3]), "r"(b0), "r"(b1));
}

__device__ __forceinline__ float sigmoidf_(float t) {
    if (t >= 0.f) { float e = __expf(-t); return 1.f / (1.f + e); }
    float e = __expf(t); return e / (1.f + e);
}

// ---------------------------------------------------------------------------
// Kernel 1: normalize anchors -> bf16 per-chunk padded tiles. grid=64, blk=128.
// ---------------------------------------------------------------------------
__global__ void __launch_bounds__(128) anchor_kernel(const float* __restrict__ kern) {
    int k = blockIdx.x;
    int tid = threadIdx.x;
    __shared__ float red[4];
    float s = 0.f;
    for (int c = tid; c < C_; c += 128) { float v = kern[k * C_ + c]; s += v * v; }
#pragma unroll
    for (int o = 16; o; o >>= 1) s += __shfl_xor_sync(0xffffffffu, s, o);
    if ((tid & 31) == 0) red[tid >> 5] = s;
    __syncthreads();
    float inv = 1.f / (sqrtf(red[0] + red[1] + red[2] + red[3]) + 1e-12f);
    for (int p = tid; p < 256; p += 128) {
        int c = p * 2;
        int kc = c >> 6, cc = c & 63;
        __nv_bfloat162 h = __floats2bfloat162_rn(kern[k * C_ + c] * inv,
                                                 kern[k * C_ + c + 1] * inv);
        *reinterpret_cast<__nv_bfloat162*>(&g_an_bf16[kc][k][cc]) = h;
    }
}

// ---------------------------------------------------------------------------
// Kernel 2: pass 1 — bf16 mma.m16n8k16 + ldmatrix, double-buffered smem,
// ONE __syncthreads per chunk, conversion at load time.
// grid = 784, block = 256 (8 warps); dynamic smem.
// smem map (bytes): A0 @0 (18432) | A1 @18432 | B0 @36864 (9216) | B1 @46080
//                   | sinv @55296 (512) | total 55808. snp overlays A0.
// ---------------------------------------------------------------------------
#define SMP1_A0 0u
#define SMP1_A1 18432u
#define SMP1_B0 36864u
#define SMP1_B1 46080u
#define SMP1_SINV 55296u
#define SMP1_TOTAL 55808

__global__ void __launch_bounds__(256) pass1_kernel(const float* __restrict__ x) {
    extern __shared__ __align__(16) char smem[];
    const uint32_t sb = smem_u32(smem);
    const int tid = threadIdx.x;
    const int lane = tid & 31, wid = tid >> 5;
    const int seg = tid & 15, rowq = tid >> 4;
    const int wr = wid * 16;

    // ldmatrix per-lane address components
    const uint32_t a_row = (uint32_t)(wr + (lane & 15));
    const uint32_t a_colb = (uint32_t)((lane >> 4) << 3);
    const uint32_t b_rowo = (uint32_t)((lane & 7) + ((lane >> 4) << 3));
    const uint32_t b_colo = (uint32_t)(lane & 8);

    const float* xg = x + (size_t)blockIdx.x * 128 * C_;
    const uint4* an4 = reinterpret_cast<const uint4*>(g_an_bf16);  // 576 uint4/chunk

    float acc[8][4];
#pragma unroll
    for (int t = 0; t < 8; t++)
#pragma unroll
        for (int i = 0; i < 4; i++) acc[t][i] = 0.f;
    float nsq = 0.f;          // per-thread partial (summed over its 8 rows x 4 cols)
    float nsqr[8];            // per-row partials
#pragma unroll
    for (int j = 0; j < 8; j++) nsqr[j] = 0.f;

    uint2 rx[8];              // converted bf16 pairs for next chunk
    uint4 rb[3];

    auto loadchunk = [&](int kc) {
#pragma unroll
        for (int j = 0; j < 8; j++) {
            float4 v = *reinterpret_cast<const float4*>(
                xg + (size_t)(rowq + 16 * j) * C_ + kc * 64 + seg * 4);
            nsqr[j] += v.x * v.x + v.y * v.y + v.z * v.z + v.w * v.w;
            __nv_bfloat162 h0 = __floats2bfloat162_rn(v.x, v.y);
            __nv_bfloat162 h1 = __floats2bfloat162_rn(v.z, v.w);
            rx[j].x = *reinterpret_cast<uint32_t*>(&h0);
            rx[j].y = *reinterpret_cast<uint32_t*>(&h1);
        }
#pragma unroll
        for (int i = 0; i < 3; i++) {
            int idx = tid + 256 * i;
            if (idx < 576) rb[i] = an4[kc * 576 + idx];
        }
    };
    auto stage = [&](uint32_t aoff, uint32_t boff) {
#pragma unroll
        for (int j = 0; j < 8; j++) {
            uint32_t off = aoff + (uint32_t)((rowq + 16 * j) * (APAD * 2) + seg * 8);
            asm volatile("st.shared.v2.b32 [%0], {%1,%2};"
                         :: "r"(sb + off), "r"(rx[j].x), "r"(rx[j].y) : "memory");
        }
#pragma unroll
        for (int i = 0; i < 3; i++) {
            int idx = tid + 256 * i;
            if (idx < 576)
                *reinterpret_cast<uint4*>(smem + boff + idx * 16) = rb[i];
        }
    };

    loadchunk(0);

#pragma unroll 1
    for (int kc = 0; kc < 8; kc++) {
        const uint32_t aoff = (kc & 1) ? SMP1_A1 : SMP1_A0;
        const uint32_t boff = (kc & 1) ? SMP1_B1 : SMP1_B0;
        stage(aoff, boff);
        __syncthreads();
        if (kc < 7) loadchunk(kc + 1);   // LDGs overlap MMA below

#pragma unroll
        for (int ks = 0; ks < 4; ks++) {
            uint32_t a[4];
            LDSM4(a[0], a[1], a[2], a[3],
                  sb + aoff + a_row * (APAD * 2) + (ks * 16 + a_colb) * 2);
#pragma unroll
            for (int nt = 0; nt < 4; nt++) {
                uint32_t b0, b1, b2, b3;
                LDSM4(b0, b1, b2, b3,
                      sb + boff + (nt * 16 + b_rowo) * (APAD * 2) + (ks * 16 + b_colo) * 2);
                mma_bf16(acc[2 * nt], a, b0, b1);
                mma_bf16(acc[2 * nt + 1], a, b2, b3);
            }
        }
        // no trailing sync: next stage targets the other buffer; the sync at
        // the top of iteration k+1 orders MMA(k) before any stage(k+2).
    }
    __syncthreads();   // all MMAs done before overlaying snp on A0

    // row norms: overlay on A0 region
    float* snp = reinterpret_cast<float*>(smem);   // [16][128]
#pragma unroll
    for (int j = 0; j < 8; j++) snp[seg * 128 + rowq + 16 * j] = nsqr[j];
    __syncthreads();
    float* sinv = reinterpret_cast<float*>(smem + SMP1_SINV);
    if (tid < 128) {
        float s2 = 0.f;
#pragma unroll
        for (int j = 0; j < 16; j++) s2 += snp[j * 128 + tid];
        sinv[tid] = 20.f / (sqrtf(s2) + 1e-12f);
    }
    __syncthreads();

    // epilogue: per-warp rows wr+g, wr+8+g fully covered within warp
    {
        const int g = lane >> 2;
        const int r0 = wr + g, r1 = wr + 8 + g;
        const float i0 = sinv[r0], i1 = sinv[r1];
        float p0 = 0.f, p1 = 0.f;
#pragma unroll
        for (int t = 0; t < 8; t++) {
            p0 += __expf(fmaf(i0, acc[t][0], -20.f)) + __expf(fmaf(i0, acc[t][1], -20.f));
            p1 += __expf(fmaf(i1, acc[t][2], -20.f)) + __expf(fmaf(i1, acc[t][3], -20.f));
        }
        p0 += __shfl_xor_sync(0xffffffffu, p0, 1);
        p0 += __shfl_xor_sync(0xffffffffu, p0, 2);
        p1 += __shfl_xor_sync(0xffffffffu, p1, 1);
        p1 += __shfl_xor_sync(0xffffffffu, p1, 2);
        if ((lane & 3) == 0) {
            g_lsS[(size_t)blockIdx.x * 128 + r0] = __logf(p0);
            g_lsS[(size_t)blockIdx.x * 128 + r1] = __logf(p1);
        }
    }
    (void)nsq;
}

// ---------------------------------------------------------------------------
// Kernel 3: per-batch Sinkhorn scalar v (10 iters) + mixing weights.
// ---------------------------------------------------------------------------
__global__ void __launch_bounds__(256) vsolve_kernel() {
    __shared__ float sl[N_];
    __shared__ float red[8];
    __shared__ float vsh;
    int b = blockIdx.x, tid = threadIdx.x;
    for (int n = tid; n < N_; n += 256) sl[n] = g_lsS[b * N_ + n];
    __syncthreads();
    float v = 0.f;
    const float logmu = logf(0.5f);
    const float logn = logf((float)N_);
    for (int it = 0; it < 10; ++it) {
        float part = 0.f;
        for (int n = tid; n < N_; n += 256) part += sigmoidf_(sl[n] + 10.f * v);
#pragma unroll
        for (int o = 16; o; o >>= 1) part += __shfl_xor_sync(0xffffffffu, part, o);
        if ((tid & 31) == 0) red[tid >> 5] = part;
        __syncthreads();
        if (tid == 0) {
            float s = 0.f;
#pragma unroll
            for (int j = 0; j < 8; j++) s += red[j];
            float m = __logf(s) - logn;
            vsh = v + 0.1f * (logmu - m);
        }
        __syncthreads();
        v = vsh;
    }
    for (int n = tid; n < N_; n += 256)
        g_mix[b * N_ + n] = 2.f * sigmoidf_(sl[n] + 10.f * v);
}

// ---------------------------------------------------------------------------
// Kernel 4a: pool stage 1 — (nsplit, batch) slice of 56 n-rows, float4 loads,
// 14-deep load batches; grid = (14, 128) = 1792 blocks (12.1/SM).
// ---------------------------------------------------------------------------
__global__ void __launch_bounds__(128) pool1_kernel(const float* __restrict__ x) {
    __shared__ float sm[NPER];
    const int ns = blockIdx.x;
    const int b = B_ - 1 - blockIdx.y;      // reverse order for L2 reuse
    const int tid = threadIdx.x;

    if (tid < NPER) sm[tid] = g_mix[b * N_ + ns * NPER + tid];
    __syncthreads();

    const float4* xb = reinterpret_cast<const float4*>(
        x + (size_t)b * N_ * C_ + (size_t)(ns * NPER) * C_) + tid;

    float4 acc[7];
#pragma unroll
    for (int j = 0; j < 7; j++) acc[j] = make_float4(0.f, 0.f, 0.f, 0.f);

#pragma unroll 1
    for (int n0 = 0; n0 < NPER; n0 += 14) {   // 56 = 4*14
        float4 v[14];
        float m[14];
#pragma unroll
        for (int j = 0; j < 14; j++) v[j] = xb[(size_t)(n0 + j) * (C_ / 4)];
#pragma unroll
        for (int j = 0; j < 14; j++) m[j] = sm[n0 + j];
#pragma unroll
        for (int j = 0; j < 7; j++) {
            acc[j].x += m[j] * v[j].x; acc[j].y += m[j] * v[j].y;
            acc[j].z += m[j] * v[j].z; acc[j].w += m[j] * v[j].w;
        }
#pragma unroll
        for (int j = 0; j < 7; j++) {
            acc[j].x += m[j + 7] * v[j + 7].x; acc[j].y += m[j + 7] * v[j + 7].y;
            acc[j].z += m[j + 7] * v[j + 7].z; acc[j].w += m[j + 7] * v[j + 7].w;
        }
    }
    float4 t;
    t.x = ((acc[0].x + acc[1].x) + (acc[2].x + acc[3].x)) + ((acc[4].x + acc[5].x) + acc[6].x);
    t.y = ((acc[0].y + acc[1].y) + (acc[2].y + acc[3].y)) + ((acc[4].y + acc[5].y) + acc[6].y);
    t.z = ((acc[0].z + acc[1].z) + (acc[2].z + acc[3].z)) + ((acc[4].z + acc[5].z) + acc[6].z);
    t.w = ((acc[0].w + acc[1].w) + (acc[2].w + acc[3].w)) + ((acc[4].w + acc[5].w) + acc[6].w);
    g_part[(size_t)ns * (B_ * C_ / 4) + b * (C_ / 4) + tid] = t;
}

// ---------------------------------------------------------------------------
// Kernel 4b: pool stage 2 — reduce NSPLIT partials, scale by 1/N.
// ---------------------------------------------------------------------------
__global__ void __launch_bounds__(256) pool2_kernel(float* __restrict__ out) {
    int i = blockIdx.x * 256 + threadIdx.x;   // 0 .. 16383
    float4 s = make_float4(0.f, 0.f, 0.f, 0.f);
#pragma unroll
    for (int p = 0; p < NSPLIT; p++) {
        float4 v = g_part[(size_t)p * (B_ * C_ / 4) + i];
        s.x += v.x; s.y += v.y; s.z += v.z; s.w += v.w;
    }
    const float inv = 1.f / (float)N_;
    s.x *= inv; s.y *= inv; s.z *= inv; s.w *= inv;
    reinterpret_cast<float4*>(out)[i] = s;
}

// ---------------------------------------------------------------------------
extern "C" void kernel_launch(void* const* d_in, const int* in_sizes, int n_in,
                              void* d_out, int out_size) {
    const float* bow = (const float*)d_in[0];
    const float* kern = (const float*)d_in[1];
    if (n_in >= 2 && in_sizes[0] < in_sizes[1]) {  // defensive: pick by size
        const float* t = bow; bow = kern; kern = t;
    }
    static bool attr_set = false;
    if (!attr_set) {
        cudaFuncSetAttribute(pass1_kernel, cudaFuncAttributeMaxDynamicSharedMemorySize,
                             SMP1_TOTAL);
        attr_set = true;
    }
    anchor_kernel<<<K_, 128>>>(kern);
    pass1_kernel<<<(B_ * N_) / 128, 256, SMP1_TOTAL>>>(bow);
    vsolve_kernel<<<B_, 256>>>();
    pool1_kernel<<<dim3(NSPLIT, B_), 128>>>(bow);
    pool2_kernel<<<64, 256>>>((float*)d_out);
}

// round 9
// speedup vs baseline: 1.0920x; 1.0920x over previous
#include <cuda_runtime.h>
#include <cuda_bf16.h>
#include <cstdint>
#include <math.h>

#define B_ 128
#define N_ 784
#define C_ 512
#define K_ 64
#define NSPLIT 8
#define NPER 98   // 784/8

// rows padded to 72 bf16 (144B) for conflict-free ldmatrix
#define APAD 72

// ---------------- scratch (no allocations allowed) -------------------------
__device__ __align__(16) __nv_bfloat16 g_an_bf16[8][K_][APAD];   // per-chunk anchor tiles
__device__ float g_lsS[B_ * N_];
__device__ float g_mix[B_ * N_];
__device__ float4 g_part[NSPLIT * B_ * C_ / 4];

__device__ __forceinline__ uint32_t smem_u32(const void* p) {
    uint32_t a;
    asm("{ .reg .u64 t; cvta.to.shared.u64 t, %1; cvt.u32.u64 %0, t; }" : "=r"(a) : "l"(p));
    return a;
}

#define LDSM4(r0, r1, r2, r3, addr) \
    asm volatile("ldmatrix.sync.aligned.m8n8.x4.shared.b16 {%0,%1,%2,%3}, [%4];" \
                 : "=r"(r0), "=r"(r1), "=r"(r2), "=r"(r3) : "r"(addr))

__device__ __forceinline__ void mma_bf16(float d[4], const uint32_t a[4],
                                         uint32_t b0, uint32_t b1) {
    asm volatile(
        "mma.sync.aligned.m16n8k16.row.col.f32.bf16.bf16.f32 "
        "{%0,%1,%2,%3}, {%4,%5,%6,%7}, {%8,%9}, {%0,%1,%2,%3};"
        : "+f"(d[0]), "+f"(d[1]), "+f"(d[2]), "+f"(d[3])
        : "r"(a[0]), "r"(a[1]), "r"(a[2]), "r"(a[3]), "r"(b0), "r"(b1));
}

__device__ __forceinline__ float sigmoidf_(float t) {
    if (t >= 0.f) { float e = __expf(-t); return 1.f / (1.f + e); }
    float e = __expf(t); return e / (1.f + e);
}

// ---------------------------------------------------------------------------
// Kernel 1: normalize anchors -> bf16 per-chunk padded tiles. grid=64, blk=128.
// ---------------------------------------------------------------------------
__global__ void __launch_bounds__(128) anchor_kernel(const float* __restrict__ kern) {
    int k = blockIdx.x;
    int tid = threadIdx.x;
    __shared__ float red[4];
    float s = 0.f;
    for (int c = tid; c < C_; c += 128) { float v = kern[k * C_ + c]; s += v * v; }
#pragma unroll
    for (int o = 16; o; o >>= 1) s += __shfl_xor_sync(0xffffffffu, s, o);
    if ((tid & 31) == 0) red[tid >> 5] = s;
    __syncthreads();
    float inv = 1.f / (sqrtf(red[0] + red[1] + red[2] + red[3]) + 1e-12f);
    for (int p = tid; p < 256; p += 128) {
        int c = p * 2;
        int kc = c >> 6, cc = c & 63;
        __nv_bfloat162 h = __floats2bfloat162_rn(kern[k * C_ + c] * inv,
                                                 kern[k * C_ + c + 1] * inv);
        *reinterpret_cast<__nv_bfloat162*>(&g_an_bf16[kc][k][cc]) = h;
    }
}

// ---------------------------------------------------------------------------
// Kernel 2: pass 1 — bf16 mma.m16n8k16 + ldmatrix, double-buffered smem,
// ONE __syncthreads per chunk. Prefetch is RAW (no consumers) so LDGs stay in
// flight across the MMA section; conversion happens at stage time.
// grid = 784, block = 256 (8 warps); dynamic smem 55808 B.
// smem map: A0 @0 (18432) | A1 @18432 | B0 @36864 (9216) | B1 @46080
//           | sinv @55296 (512). snp overlays A0 after the mainloop.
// ---------------------------------------------------------------------------
#define SMP1_A0 0u
#define SMP1_A1 18432u
#define SMP1_B0 36864u
#define SMP1_B1 46080u
#define SMP1_SINV 55296u
#define SMP1_TOTAL 55808

__global__ void __launch_bounds__(256) pass1_kernel(const float* __restrict__ x) {
    extern __shared__ __align__(16) char smem[];
    const uint32_t sb = smem_u32(smem);
    const int tid = threadIdx.x;
    const int lane = tid & 31, wid = tid >> 5;
    const int seg = tid & 15, rowq = tid >> 4;
    const int wr = wid * 16;

    // ldmatrix per-lane address components
    const uint32_t a_row = (uint32_t)(wr + (lane & 15));
    const uint32_t a_colb = (uint32_t)((lane >> 4) << 3);
    const uint32_t b_rowo = (uint32_t)((lane & 7) + ((lane >> 4) << 3));
    const uint32_t b_colo = (uint32_t)(lane & 8);

    const float* xg = x + (size_t)blockIdx.x * 128 * C_;
    const uint4* an4 = reinterpret_cast<const uint4*>(g_an_bf16);  // 576 uint4/chunk

    float acc[8][4];
#pragma unroll
    for (int t = 0; t < 8; t++)
#pragma unroll
        for (int i = 0; i < 4; i++) acc[t][i] = 0.f;
    float nsqr[8];
#pragma unroll
    for (int j = 0; j < 8; j++) nsqr[j] = 0.f;

    float4 rx[8];     // RAW prefetched floats (no consumer until stage)
    uint4 rb[3];

    auto prefetch = [&](int kc) {       // pure LDG, nothing consumes results
#pragma unroll
        for (int j = 0; j < 8; j++)
            rx[j] = *reinterpret_cast<const float4*>(
                xg + (size_t)(rowq + 16 * j) * C_ + kc * 64 + seg * 4);
#pragma unroll
        for (int i = 0; i < 3; i++) {
            int idx = tid + 256 * i;
            if (idx < 576) rb[i] = an4[kc * 576 + idx];
        }
    };
    auto stage = [&](uint32_t aoff, uint32_t boff) {  // convert + norms + STS
#pragma unroll
        for (int j = 0; j < 8; j++) {
            float4 v = rx[j];
            nsqr[j] += v.x * v.x + v.y * v.y + v.z * v.z + v.w * v.w;
            __nv_bfloat162 h0 = __floats2bfloat162_rn(v.x, v.y);
            __nv_bfloat162 h1 = __floats2bfloat162_rn(v.z, v.w);
            uint32_t u0 = *reinterpret_cast<uint32_t*>(&h0);
            uint32_t u1 = *reinterpret_cast<uint32_t*>(&h1);
            uint32_t off = aoff + (uint32_t)((rowq + 16 * j) * (APAD * 2) + seg * 8);
            asm volatile("st.shared.v2.b32 [%0], {%1,%2};"
                         :: "r"(sb + off), "r"(u0), "r"(u1) : "memory");
        }
#pragma unroll
        for (int i = 0; i < 3; i++) {
            int idx = tid + 256 * i;
            if (idx < 576)
                *reinterpret_cast<uint4*>(smem + boff + idx * 16) = rb[i];
        }
    };

    prefetch(0);

#pragma unroll 1
    for (int kc = 0; kc < 8; kc++) {
        const uint32_t aoff = (kc & 1) ? SMP1_A1 : SMP1_A0;
        const uint32_t boff = (kc & 1) ? SMP1_B1 : SMP1_B0;
        stage(aoff, boff);
        __syncthreads();
        if (kc < 7) prefetch(kc + 1);    // LDGs overlap MMAs below

#pragma unroll
        for (int ks = 0; ks < 4; ks++) {
            uint32_t a[4];
            LDSM4(a[0], a[1], a[2], a[3],
                  sb + aoff + a_row * (APAD * 2) + (ks * 16 + a_colb) * 2);
#pragma unroll
            for (int nt = 0; nt < 4; nt++) {
                uint32_t b0, b1, b2, b3;
                LDSM4(b0, b1, b2, b3,
                      sb + boff + (nt * 16 + b_rowo) * (APAD * 2) + (ks * 16 + b_colo) * 2);
                mma_bf16(acc[2 * nt], a, b0, b1);
                mma_bf16(acc[2 * nt + 1], a, b2, b3);
            }
        }
        // no trailing sync: next stage targets the other buffer; the sync at
        // the top of iteration k+1 orders MMA(k) before any stage(k+2).
    }
    __syncthreads();   // all MMAs done before overlaying snp on A0

    // row norms: overlay on A0 region
    float* snp = reinterpret_cast<float*>(smem);   // [16][128]
#pragma unroll
    for (int j = 0; j < 8; j++) snp[seg * 128 + rowq + 16 * j] = nsqr[j];
    __syncthreads();
    float* sinv = reinterpret_cast<float*>(smem + SMP1_SINV);
    if (tid < 128) {
        float s2 = 0.f;
#pragma unroll
        for (int j = 0; j < 16; j++) s2 += snp[j * 128 + tid];
        sinv[tid] = 20.f / (sqrtf(s2) + 1e-12f);
    }
    __syncthreads();

    // epilogue: per-warp rows wr+g, wr+8+g fully covered within warp
    {
        const int g = lane >> 2;
        const int r0 = wr + g, r1 = wr + 8 + g;
        const float i0 = sinv[r0], i1 = sinv[r1];
        float p0 = 0.f, p1 = 0.f;
#pragma unroll
        for (int t = 0; t < 8; t++) {
            p0 += __expf(fmaf(i0, acc[t][0], -20.f)) + __expf(fmaf(i0, acc[t][1], -20.f));
            p1 += __expf(fmaf(i1, acc[t][2], -20.f)) + __expf(fmaf(i1, acc[t][3], -20.f));
        }
        p0 += __shfl_xor_sync(0xffffffffu, p0, 1);
        p0 += __shfl_xor_sync(0xffffffffu, p0, 2);
        p1 += __shfl_xor_sync(0xffffffffu, p1, 1);
        p1 += __shfl_xor_sync(0xffffffffu, p1, 2);
        if ((lane & 3) == 0) {
            g_lsS[(size_t)blockIdx.x * 128 + r0] = __logf(p0);
            g_lsS[(size_t)blockIdx.x * 128 + r1] = __logf(p1);
        }
    }
}

// ---------------------------------------------------------------------------
// Kernel 3: per-batch Sinkhorn scalar v (10 iters) + mixing weights.
// ---------------------------------------------------------------------------
__global__ void __launch_bounds__(256) vsolve_kernel() {
    __shared__ float sl[N_];
    __shared__ float red[8];
    __shared__ float vsh;
    int b = blockIdx.x, tid = threadIdx.x;
    for (int n = tid; n < N_; n += 256) sl[n] = g_lsS[b * N_ + n];
    __syncthreads();
    float v = 0.f;
    const float logmu = logf(0.5f);
    const float logn = logf((float)N_);
    for (int it = 0; it < 10; ++it) {
        float part = 0.f;
        for (int n = tid; n < N_; n += 256) part += sigmoidf_(sl[n] + 10.f * v);
#pragma unroll
        for (int o = 16; o; o >>= 1) part += __shfl_xor_sync(0xffffffffu, part, o);
        if ((tid & 31) == 0) red[tid >> 5] = part;
        __syncthreads();
        if (tid == 0) {
            float s = 0.f;
#pragma unroll
            for (int j = 0; j < 8; j++) s += red[j];
            float m = __logf(s) - logn;
            vsh = v + 0.1f * (logmu - m);
        }
        __syncthreads();
        v = vsh;
    }
    for (int n = tid; n < N_; n += 256)
        g_mix[b * N_ + n] = 2.f * sigmoidf_(sl[n] + 10.f * v);
}

// ---------------------------------------------------------------------------
// Kernel 4a: pool stage 1 — (nsplit, batch) slice of 98 n-rows, float4 loads,
// 14-deep load batches, reversed batch order for L2 reuse. grid=(8,128).
// ---------------------------------------------------------------------------
__global__ void __launch_bounds__(128) pool1_kernel(const float* __restrict__ x) {
    __shared__ float sm[NPER];
    const int ns = blockIdx.x;
    const int b = B_ - 1 - blockIdx.y;
    const int tid = threadIdx.x;

    if (tid < NPER) sm[tid] = g_mix[b * N_ + ns * NPER + tid];
    __syncthreads();

    const float4* xb = reinterpret_cast<const float4*>(
        x + (size_t)b * N_ * C_ + (size_t)(ns * NPER) * C_) + tid;

    float4 acc[7];
#pragma unroll
    for (int j = 0; j < 7; j++) acc[j] = make_float4(0.f, 0.f, 0.f, 0.f);

#pragma unroll 1
    for (int n0 = 0; n0 < NPER; n0 += 14) {   // 98 = 7*14
        float4 v[14];
        float m[14];
#pragma unroll
        for (int j = 0; j < 14; j++) v[j] = xb[(size_t)(n0 + j) * (C_ / 4)];
#pragma unroll
        for (int j = 0; j < 14; j++) m[j] = sm[n0 + j];
#pragma unroll
        for (int j = 0; j < 7; j++) {
            acc[j].x += m[j] * v[j].x; acc[j].y += m[j] * v[j].y;
            acc[j].z += m[j] * v[j].z; acc[j].w += m[j] * v[j].w;
        }
#pragma unroll
        for (int j = 0; j < 7; j++) {
            acc[j].x += m[j + 7] * v[j + 7].x; acc[j].y += m[j + 7] * v[j + 7].y;
            acc[j].z += m[j + 7] * v[j + 7].z; acc[j].w += m[j + 7] * v[j + 7].w;
        }
    }
    float4 t;
    t.x = ((acc[0].x + acc[1].x) + (acc[2].x + acc[3].x)) + ((acc[4].x + acc[5].x) + acc[6].x);
    t.y = ((acc[0].y + acc[1].y) + (acc[2].y + acc[3].y)) + ((acc[4].y + acc[5].y) + acc[6].y);
    t.z = ((acc[0].z + acc[1].z) + (acc[2].z + acc[3].z)) + ((acc[4].z + acc[5].z) + acc[6].z);
    t.w = ((acc[0].w + acc[1].w) + (acc[2].w + acc[3].w)) + ((acc[4].w + acc[5].w) + acc[6].w);
    g_part[(size_t)ns * (B_ * C_ / 4) + b * (C_ / 4) + tid] = t;
}

// ---------------------------------------------------------------------------
// Kernel 4b: pool stage 2 — reduce NSPLIT partials, scale by 1/N.
// ---------------------------------------------------------------------------
__global__ void __launch_bounds__(256) pool2_kernel(float* __restrict__ out) {
    int i = blockIdx.x * 256 + threadIdx.x;   // 0 .. 16383
    float4 s = make_float4(0.f, 0.f, 0.f, 0.f);
#pragma unroll
    for (int p = 0; p < NSPLIT; p++) {
        float4 v = g_part[(size_t)p * (B_ * C_ / 4) + i];
        s.x += v.x; s.y += v.y; s.z += v.z; s.w += v.w;
    }
    const float inv = 1.f / (float)N_;
    s.x *= inv; s.y *= inv; s.z *= inv; s.w *= inv;
    reinterpret_cast<float4*>(out)[i] = s;
}

// ---------------------------------------------------------------------------
extern "C" void kernel_launch(void* const* d_in, const int* in_sizes, int n_in,
                              void* d_out, int out_size) {
    const float* bow = (const float*)d_in[0];
    const float* kern = (const float*)d_in[1];
    if (n_in >= 2 && in_sizes[0] < in_sizes[1]) {  // defensive: pick by size
        const float* t = bow; bow = kern; kern = t;
    }
    static bool attr_set = false;
    if (!attr_set) {
        cudaFuncSetAttribute(pass1_kernel, cudaFuncAttributeMaxDynamicSharedMemorySize,
                             SMP1_TOTAL);
        attr_set = true;
    }
    anchor_kernel<<<K_, 128>>>(kern);
    pass1_kernel<<<(B_ * N_) / 128, 256, SMP1_TOTAL>>>(bow);
    vsolve_kernel<<<B_, 256>>>();
    pool1_kernel<<<dim3(NSPLIT, B_), 128>>>(bow);
    pool2_kernel<<<64, 256>>>((float*)d_out);
}